// round 6
// baseline (speedup 1.0000x reference)
#include <cuda_runtime.h>
#include <cstdint>
#include <cstddef>

// out[n, l, o] = weight[o, l]   for n in [0,128), l,o in [0,1024)
// 512 MB broadcast-write of weight.T. 8192 fine-grained blocks (backfill),
// transposed tile held in registers, replicated over n.
// Round 6 probe: write-through stores (__stwt) to feed the DRAM write queue
// directly instead of via bursty L2 dirty-eviction (DRAM stuck at 79% busy).

namespace {
constexpr int L   = 1024;
constexpr int OUT = 1024;
constexpr int N   = 128;

constexpr int TL = 32;   // tile extent along l
constexpr int TO = 64;   // tile extent along o
constexpr int NZ = 16;   // grid (32,16,16) = 8192 blocks
constexpr int N_PER_BLOCK = N / NZ;  // 8
constexpr int THREADS = 256;
}

__global__ __launch_bounds__(THREADS)
void linfwddiff_bcast_wt(const float* __restrict__ w,
                         float* __restrict__ out) {
    // Padded transpose tile: tile[l][o]; row stride 68 floats (no bank conflicts).
    __shared__ __align__(16) float tile[TL][TO + 4];

    const int l0 = blockIdx.x * TL;
    const int o0 = blockIdx.y * TO;
    const int n0 = blockIdx.z * N_PER_BLOCK;
    const int tid = threadIdx.x;

    // ---- Load weight tile [o0:o0+64, l0:l0+32], transposing into smem ----
#pragma unroll
    for (int i = 0; i < 2; i++) {
        const int slot = tid + i * THREADS;
        const int r = slot >> 3;      // o offset within tile: 0..63
        const int c = slot & 7;       // l float4 column:      0..7
        const float4 v = *reinterpret_cast<const float4*>(
            &w[(size_t)(o0 + r) * L + l0 + c * 4]);
        tile[c * 4 + 0][r] = v.x;
        tile[c * 4 + 1][r] = v.y;
        tile[c * 4 + 2][r] = v.z;
        tile[c * 4 + 3][r] = v.w;
    }
    __syncthreads();

    // ---- Hoist transposed values into registers (2 float4 per thread) ----
    const int slot0 = tid;
    const int slot1 = tid + THREADS;
    const int l_a = slot0 >> 4, c_a = slot0 & 15;
    const int l_b = slot1 >> 4, c_b = slot1 & 15;
    const float4 va = *reinterpret_cast<const float4*>(&tile[l_a][c_a * 4]);
    const float4 vb = *reinterpret_cast<const float4*>(&tile[l_b][c_b * 4]);

    const size_t plane = (size_t)L * OUT;                       // 1M elements
    const size_t offa = (size_t)(l0 + l_a) * OUT + o0 + c_a * 4;
    const size_t offb = (size_t)(l0 + l_b) * OUT + o0 + c_b * 4;
    size_t base = (size_t)n0 * plane;

    // ---- Replicate-store across n: pure STG.128 write-through stream ----
#pragma unroll
    for (int n = 0; n < N_PER_BLOCK; n++) {
        __stwt(reinterpret_cast<float4*>(&out[base + offa]), va);
        __stwt(reinterpret_cast<float4*>(&out[base + offb]), vb);
        base += plane;
    }
}

extern "C" void kernel_launch(void* const* d_in, const int* in_sizes, int n_in,
                              void* d_out, int out_size) {
    // d_in[0] = x (unused — reference discards net(x)), d_in[1] = weight [1024,1024]
    const float* weight = (const float*)d_in[1];
    float* out = (float*)d_out;

    dim3 grid(L / TL, OUT / TO, NZ);   // (32, 16, 16) = 8192 blocks
    linfwddiff_bcast_wt<<<grid, THREADS>>>(weight, out);
}

// round 7
// speedup vs baseline: 1.1556x; 1.1556x over previous
#include <cuda_runtime.h>
#include <cstdint>
#include <cstddef>

// out[n, l, o] = weight[o, l]   for n in [0,128), l,o in [0,1024)
// 512 MB broadcast-write of weight.T, transposed tile held in registers.
// Proven optimum: __stcs evict-first streaming + fine-grained oversubscription.
// Round 7: NZ 16 -> 32 (16384 blocks, 4 planes each) to halve the drain-tail
// granularity (R1->R3 showed monotone gain from finer blocks).

namespace {
constexpr int L   = 1024;
constexpr int OUT = 1024;
constexpr int N   = 128;

constexpr int TL = 32;   // tile extent along l
constexpr int TO = 64;   // tile extent along o
constexpr int NZ = 32;   // grid (32,16,32) = 16384 blocks
constexpr int N_PER_BLOCK = N / NZ;  // 4 planes per block
constexpr int THREADS = 256;
}

__global__ __launch_bounds__(THREADS)
void linfwddiff_bcast_fine32(const float* __restrict__ w,
                             float* __restrict__ out) {
    // Padded transpose tile: tile[l][o]; row stride 68 floats (no bank conflicts).
    __shared__ __align__(16) float tile[TL][TO + 4];

    const int l0 = blockIdx.x * TL;
    const int o0 = blockIdx.y * TO;
    const int n0 = blockIdx.z * N_PER_BLOCK;
    const int tid = threadIdx.x;

    // ---- Load weight tile [o0:o0+64, l0:l0+32], transposing into smem ----
    // 64 rows (o) x 8 float4 (l) = 512 slots; 256 threads, 2 slots each.
#pragma unroll
    for (int i = 0; i < 2; i++) {
        const int slot = tid + i * THREADS;
        const int r = slot >> 3;      // o offset within tile: 0..63
        const int c = slot & 7;       // l float4 column:      0..7
        const float4 v = *reinterpret_cast<const float4*>(
            &w[(size_t)(o0 + r) * L + l0 + c * 4]);
        tile[c * 4 + 0][r] = v.x;
        tile[c * 4 + 1][r] = v.y;
        tile[c * 4 + 2][r] = v.z;
        tile[c * 4 + 3][r] = v.w;
    }
    __syncthreads();

    // ---- Hoist transposed values into registers (2 float4 per thread) ----
    // 32 rows (l) x 16 float4 (o) = 512 slots; 2 per thread.
    const int slot0 = tid;
    const int slot1 = tid + THREADS;
    const int l_a = slot0 >> 4, c_a = slot0 & 15;
    const int l_b = slot1 >> 4, c_b = slot1 & 15;
    const float4 va = *reinterpret_cast<const float4*>(&tile[l_a][c_a * 4]);
    const float4 vb = *reinterpret_cast<const float4*>(&tile[l_b][c_b * 4]);

    const size_t plane = (size_t)L * OUT;                       // 1M elements
    const size_t offa = (size_t)(l0 + l_a) * OUT + o0 + c_a * 4;
    const size_t offb = (size_t)(l0 + l_b) * OUT + o0 + c_b * 4;
    size_t base = (size_t)n0 * plane;

    // ---- Replicate-store across n: pure STG.128 stream, evict-first ----
#pragma unroll
    for (int n = 0; n < N_PER_BLOCK; n++) {
        __stcs(reinterpret_cast<float4*>(&out[base + offa]), va);
        __stcs(reinterpret_cast<float4*>(&out[base + offb]), vb);
        base += plane;
    }
}

extern "C" void kernel_launch(void* const* d_in, const int* in_sizes, int n_in,
                              void* d_out, int out_size) {
    // d_in[0] = x (unused — reference discards net(x)), d_in[1] = weight [1024,1024]
    const float* weight = (const float*)d_in[1];
    float* out = (float*)d_out;

    dim3 grid(L / TL, OUT / TO, NZ);   // (32, 16, 32) = 16384 blocks
    linfwddiff_bcast_fine32<<<grid, THREADS>>>(weight, out);
}

// round 8
// speedup vs baseline: 1.1661x; 1.0091x over previous
#include <cuda_runtime.h>
#include <cstdint>
#include <cstddef>

// out[n, l, o] = weight[o, l]   for n in [0,128), l,o in [0,1024)
// 512 MB broadcast-write of weight.T, transposed tile held in registers.
// Proven: __stcs streaming + fine-grained oversubscription (DRAM duty rises
// monotonically with block count: 4096->79.1%, 8192->79.5%, 16384->81.5%).
// Round 8: 32768 blocks via finer o-tile (TO 64->32), which doubles
// granularity WITHOUT growing redundant weight re-reads (those scale with NZ).

namespace {
constexpr int L   = 1024;
constexpr int OUT = 1024;
constexpr int N   = 128;

constexpr int TL = 32;   // tile extent along l
constexpr int TO = 32;   // tile extent along o (halved vs R7)
constexpr int NZ = 32;   // grid (32,32,32) = 32768 blocks
constexpr int N_PER_BLOCK = N / NZ;  // 4 planes per block
constexpr int THREADS = 256;
}

__global__ __launch_bounds__(THREADS)
void linfwddiff_bcast_fine32x32(const float* __restrict__ w,
                                float* __restrict__ out) {
    // Padded transpose tile: tile[l][o]; row stride 36 floats (no bank conflicts).
    __shared__ __align__(16) float tile[TL][TO + 4];

    const int l0 = blockIdx.x * TL;
    const int o0 = blockIdx.y * TO;
    const int n0 = blockIdx.z * N_PER_BLOCK;
    const int tid = threadIdx.x;

    // ---- Load weight tile [o0:o0+32, l0:l0+32], transposing into smem ----
    // 32 rows (o) x 8 float4 (l) = 256 slots; 1 per thread.
    {
        const int r = tid >> 3;       // o offset within tile: 0..31
        const int c = tid & 7;        // l float4 column:      0..7
        const float4 v = *reinterpret_cast<const float4*>(
            &w[(size_t)(o0 + r) * L + l0 + c * 4]);
        tile[c * 4 + 0][r] = v.x;
        tile[c * 4 + 1][r] = v.y;
        tile[c * 4 + 2][r] = v.z;
        tile[c * 4 + 3][r] = v.w;
    }
    __syncthreads();

    // ---- Hoist transposed values into registers (1 float4 per thread) ----
    // 32 rows (l) x 8 float4 (o) = 256 slots; 1 per thread.
    const int l_a = tid >> 3;         // l within tile: 0..31
    const int c_a = tid & 7;          // o float4 column: 0..7
    const float4 va = *reinterpret_cast<const float4*>(&tile[l_a][c_a * 4]);

    const size_t plane = (size_t)L * OUT;                       // 1M elements
    const size_t offa = (size_t)(l0 + l_a) * OUT + o0 + c_a * 4;
    size_t base = (size_t)n0 * plane;

    // ---- Replicate-store across n: pure STG.128 stream, evict-first ----
#pragma unroll
    for (int n = 0; n < N_PER_BLOCK; n++) {
        __stcs(reinterpret_cast<float4*>(&out[base + offa]), va);
        base += plane;
    }
}

extern "C" void kernel_launch(void* const* d_in, const int* in_sizes, int n_in,
                              void* d_out, int out_size) {
    // d_in[0] = x (unused — reference discards net(x)), d_in[1] = weight [1024,1024]
    const float* weight = (const float*)d_in[1];
    float* out = (float*)d_out;

    dim3 grid(L / TL, OUT / TO, NZ);   // (32, 32, 32) = 32768 blocks
    linfwddiff_bcast_fine32x32<<<grid, THREADS>>>(weight, out);
}